// round 1
// baseline (speedup 1.0000x reference)
#include <cuda_runtime.h>

#define NNODES 100000
#define NEDGES 3200000
#define INCH 128
#define HID 64

// ---------------- scratch (static device globals; no allocs allowed) ----------------
__device__ float d_g[(size_t)NNODES * HID];    // dinv-scaled features (scatter source)
__device__ float d_acc[(size_t)NNODES * HID];  // scatter accumulator
__device__ float d_h[(size_t)NNODES * HID];    // layer intermediate
__device__ float d_deg[NNODES];
__device__ float d_dinv[NNODES];
__device__ int   d_row[NEDGES];
__device__ int   d_col[NEDGES];
__device__ int   g_idx64;

// ---------------- helpers ----------------
__device__ __forceinline__ void red_add_v4(float* addr, float4 v) {
    asm volatile("red.global.add.v4.f32 [%0], {%1, %2, %3, %4};"
                 :: "l"(addr), "f"(v.x), "f"(v.y), "f"(v.z), "f"(v.w)
                 : "memory");
}

// ---------------- dtype detection: int64 edge_index has zero high words ----------------
__global__ void detect_kernel(const unsigned* __restrict__ ei) {
    unsigned v = 0;
    int i = threadIdx.x; // 32 threads, each checks 4 candidate high-words
#pragma unroll
    for (int s = 0; s < 4; ++s) v |= ei[(size_t)(i * 4 + s) * 2 + 1];
    unsigned any = __ballot_sync(0xffffffffu, v != 0);
    if (threadIdx.x == 0) g_idx64 = (any == 0) ? 1 : 0;
}

__global__ void convert_kernel(const void* __restrict__ ei, int E) {
    int i = blockIdx.x * blockDim.x + threadIdx.x;
    if (i >= E) return;
    if (g_idx64) {
        const long long* p = (const long long*)ei;
        d_row[i] = (int)p[i];
        d_col[i] = (int)p[(size_t)E + i];
    } else {
        const int* p = (const int*)ei;
        d_row[i] = p[i];
        d_col[i] = p[(size_t)E + i];
    }
}

// ---------------- degree / dinv ----------------
__global__ void init_deg_kernel(int n) {
    int i = blockIdx.x * blockDim.x + threadIdx.x;
    if (i < n) d_deg[i] = 1.0f; // self loop
}

__global__ void count_deg_kernel(int E) {
    int i = blockIdx.x * blockDim.x + threadIdx.x;
    if (i < E) atomicAdd(&d_deg[d_col[i]], 1.0f);
}

__global__ void dinv_kernel(int n) {
    int i = blockIdx.x * blockDim.x + threadIdx.x;
    if (i < n) d_dinv[i] = rsqrtf(d_deg[i]);
}

// ---------------- zero accumulator ----------------
__global__ void zero_kernel(float4* __restrict__ p, int n4) {
    int i = blockIdx.x * blockDim.x + threadIdx.x;
    if (i < n4) p[i] = make_float4(0.f, 0.f, 0.f, 0.f);
}

// ---------------- GEMM: C[i,:] = act( (A[i,:] @ W) * (SCALE?dinv[i]:1) + (BIAS?b:0) ) ----------------
template<int K, int NC, bool RELU, bool BIAS, bool SCALE>
__global__ void gemm_kernel(const float* __restrict__ A, const float* __restrict__ W,
                            const float* __restrict__ bias, float* __restrict__ C, int nrows) {
    constexpr int CG  = NC / 16;   // col-groups of 16
    constexpr int RPB = 256 / CG;  // rows per block
    __shared__ float Ws[K * NC];
    for (int t = threadIdx.x; t < K * NC / 4; t += 256)
        ((float4*)Ws)[t] = ((const float4*)W)[t];
    __syncthreads();

    int r  = blockIdx.x * RPB + threadIdx.x / CG;
    int cg = threadIdx.x % CG;
    if (r >= nrows) return;

    const float4* Arow = (const float4*)(A + (size_t)r * K);
    float acc[16];
#pragma unroll
    for (int j = 0; j < 16; ++j) acc[j] = 0.f;

#pragma unroll
    for (int k4 = 0; k4 < K / 4; ++k4) {
        float4 a = Arow[k4];
#pragma unroll
        for (int s = 0; s < 4; ++s) {
            float av = (s == 0) ? a.x : (s == 1) ? a.y : (s == 2) ? a.z : a.w;
            int k = k4 * 4 + s;
            const float4* w = (const float4*)&Ws[k * NC + cg * 16];
            float4 w0 = w[0], w1 = w[1], w2 = w[2], w3 = w[3];
            acc[0]  += av * w0.x; acc[1]  += av * w0.y; acc[2]  += av * w0.z; acc[3]  += av * w0.w;
            acc[4]  += av * w1.x; acc[5]  += av * w1.y; acc[6]  += av * w1.z; acc[7]  += av * w1.w;
            acc[8]  += av * w2.x; acc[9]  += av * w2.y; acc[10] += av * w2.z; acc[11] += av * w2.w;
            acc[12] += av * w3.x; acc[13] += av * w3.y; acc[14] += av * w3.z; acc[15] += av * w3.w;
        }
    }

    float sc = SCALE ? d_dinv[r] : 1.0f;
    float* Crow = C + (size_t)r * NC + cg * 16;
#pragma unroll
    for (int j = 0; j < 16; ++j) {
        float v = acc[j] * sc;
        if (BIAS) v += bias[cg * 16 + j];
        if (RELU) v = fmaxf(v, 0.f);
        Crow[j] = v;
    }
}

// ---------------- edge scatter: acc[col] += g[row] (64 floats, 16 threads/edge) ----------------
__global__ void scatter_kernel(int E) {
    int tid = blockIdx.x * blockDim.x + threadIdx.x;
    int e = tid >> 4;
    if (e >= E) return;
    int l = tid & 15;
    int r = d_row[e];
    int c = d_col[e];
    float4 v = *(const float4*)&d_g[(size_t)r * HID + l * 4];
    red_add_v4(&d_acc[(size_t)c * HID + l * 4], v);
}

// ---------------- out[i,:] = relu( dinv[i]*(acc[i,:] + g[i,:]) + b ) ----------------
__global__ void finalize_kernel(const float* __restrict__ b, float* __restrict__ out, int n) {
    int idx = blockIdx.x * blockDim.x + threadIdx.x; // over n*16 float4 groups
    if (idx >= n * 16) return;
    int i  = idx >> 4;
    int j4 = idx & 15;
    float4 a  = *(const float4*)&d_acc[(size_t)idx * 4];
    float4 g  = *(const float4*)&d_g[(size_t)idx * 4];
    float  di = d_dinv[i];
    float4 bb = *(const float4*)&b[j4 * 4];
    float4 o;
    o.x = fmaxf(di * (a.x + g.x) + bb.x, 0.f);
    o.y = fmaxf(di * (a.y + g.y) + bb.y, 0.f);
    o.z = fmaxf(di * (a.z + g.z) + bb.z, 0.f);
    o.w = fmaxf(di * (a.w + g.w) + bb.w, 0.f);
    *(float4*)&out[(size_t)idx * 4] = o;
}

// ---------------- edge scores: es[e] = dot(nr[row[e]], nr[col[e]]) ----------------
__global__ void escore_kernel(const float* __restrict__ nr, float* __restrict__ es, int E) {
    int tid = blockIdx.x * blockDim.x + threadIdx.x;
    int e = tid >> 4;
    if (e >= E) return;
    int l = tid & 15;
    int r = d_row[e];
    int c = d_col[e];
    float4 a = *(const float4*)&nr[(size_t)r * HID + l * 4];
    float4 b = *(const float4*)&nr[(size_t)c * HID + l * 4];
    float s = a.x * b.x + a.y * b.y + a.z * b.z + a.w * b.w;
    s += __shfl_xor_sync(0xffffffffu, s, 8);
    s += __shfl_xor_sync(0xffffffffu, s, 4);
    s += __shfl_xor_sync(0xffffffffu, s, 2);
    s += __shfl_xor_sync(0xffffffffu, s, 1);
    if (l == 0) es[e] = s;
}

// ---------------- launch ----------------
extern "C" void kernel_launch(void* const* d_in, const int* in_sizes, int n_in,
                              void* d_out, int out_size) {
    const float* x   = (const float*)d_in[0];
    const void*  ei  = d_in[1];
    const float* W1  = (const float*)d_in[2];
    const float* b1  = (const float*)d_in[3];
    const float* W2  = (const float*)d_in[4];
    const float* b2  = (const float*)d_in[5];
    const float* Wd1 = (const float*)d_in[6];
    const float* bd1 = (const float*)d_in[7];
    const float* Wd2 = (const float*)d_in[8];
    const float* bd2 = (const float*)d_in[9];
    float* out = (float*)d_out;

    int Nn = in_sizes[0] / INCH; // 100000
    int Ee = in_sizes[1] / 2;    // 3200000

    float* out_rx = out;
    float* out_es = out + (size_t)Nn * INCH;
    float* out_nr = out_es + (size_t)Ee;

    float *pg = nullptr, *pacc = nullptr, *ph = nullptr;
    cudaGetSymbolAddress((void**)&pg,   d_g);
    cudaGetSymbolAddress((void**)&pacc, d_acc);
    cudaGetSymbolAddress((void**)&ph,   d_h);

    const int T = 256;
    int ebl   = (Ee + T - 1) / T;
    int nbl   = (Nn + T - 1) / T;
    int e16bl = (int)(((size_t)Ee * 16 + T - 1) / T);
    int n16bl = (int)(((size_t)Nn * 16 + T - 1) / T);
    int n4bl  = (int)(((size_t)Nn * HID / 4 + T - 1) / T);

    // edge index preprocessing + degrees
    detect_kernel<<<1, 32>>>((const unsigned*)ei);
    convert_kernel<<<ebl, T>>>(ei, Ee);
    init_deg_kernel<<<nbl, T>>>(Nn);
    count_deg_kernel<<<ebl, T>>>(Ee);
    dinv_kernel<<<nbl, T>>>(Nn);

    // ---- layer 1: g = (x@W1)*dinv ; acc = scatter(g) ; h = relu(dinv*(acc+g)+b1)
    gemm_kernel<INCH, HID, false, false, true><<<(Nn + 63) / 64, T>>>(x, W1, nullptr, pg, Nn);
    zero_kernel<<<n4bl, T>>>((float4*)pacc, Nn * HID / 4);
    scatter_kernel<<<e16bl, T>>>(Ee);
    finalize_kernel<<<n16bl, T>>>(b1, ph, Nn);

    // ---- layer 2 -> node_representation (written straight into out segment)
    gemm_kernel<HID, HID, false, false, true><<<(Nn + 63) / 64, T>>>(ph, W2, nullptr, pg, Nn);
    zero_kernel<<<n4bl, T>>>((float4*)pacc, Nn * HID / 4);
    scatter_kernel<<<e16bl, T>>>(Ee);
    finalize_kernel<<<n16bl, T>>>(b2, out_nr, Nn);

    // ---- decoder: rec = relu(nr@Wd1+bd1) ; rx = rec@Wd2 + bd2
    gemm_kernel<HID, HID, true, true, false><<<(Nn + 63) / 64, T>>>(out_nr, Wd1, bd1, ph, Nn);
    gemm_kernel<HID, INCH, false, true, false><<<(Nn + 31) / 32, T>>>(ph, Wd2, bd2, out_rx, Nn);

    // ---- edge scores
    escore_kernel<<<e16bl, T>>>(out_nr, out_es, Ee);
}

// round 2
// speedup vs baseline: 1.9090x; 1.9090x over previous
#include <cuda_runtime.h>

#define NNODES 100000
#define NEDGES 3200000
#define INCH 128
#define HID 64

// ---------------- scratch (static device globals; no allocs allowed) ----------------
__device__ float d_g[(size_t)NNODES * HID];    // dinv-scaled features (scatter source)
__device__ float d_acc[(size_t)NNODES * HID];  // scatter accumulator
__device__ float d_h[(size_t)NNODES * HID];    // layer intermediate
__device__ float d_deg[NNODES];
__device__ float d_dinv[NNODES];
__device__ int   d_row[NEDGES];
__device__ int   d_col[NEDGES];
__device__ int   g_idx64;

// ---------------- helpers ----------------
__device__ __forceinline__ void red_add_v4(float* addr, float4 v) {
    asm volatile("red.global.add.v4.f32 [%0], {%1, %2, %3, %4};"
                 :: "l"(addr), "f"(v.x), "f"(v.y), "f"(v.z), "f"(v.w)
                 : "memory");
}

__device__ __forceinline__ unsigned long long pack2(float v) {
    unsigned long long r;
    asm("mov.b64 %0, {%1, %1};" : "=l"(r) : "f"(v));
    return r;
}

__device__ __forceinline__ void fma2(unsigned long long& acc, unsigned long long a,
                                     unsigned long long b) {
    asm("fma.rn.f32x2 %0, %1, %2, %0;" : "+l"(acc) : "l"(a), "l"(b));
}

__device__ __forceinline__ float2 unpack2(unsigned long long v) {
    float2 r;
    asm("mov.b64 {%0, %1}, %2;" : "=f"(r.x), "=f"(r.y) : "l"(v));
    return r;
}

// ---------------- dtype detection: int64 edge_index has zero high words ----------------
__global__ void detect_kernel(const unsigned* __restrict__ ei) {
    unsigned v = 0;
    int i = threadIdx.x;
#pragma unroll
    for (int s = 0; s < 4; ++s) v |= ei[(size_t)(i * 4 + s) * 2 + 1];
    unsigned any = __ballot_sync(0xffffffffu, v != 0);
    if (threadIdx.x == 0) g_idx64 = (any == 0) ? 1 : 0;
}

// ---------------- convert + degree count fused (deg must be pre-initialized) --------
__global__ void convert_kernel(const void* __restrict__ ei, int E) {
    int i = blockIdx.x * blockDim.x + threadIdx.x;
    if (i >= E) return;
    int r, c;
    if (g_idx64) {
        const long long* p = (const long long*)ei;
        r = (int)p[i];
        c = (int)p[(size_t)E + i];
    } else {
        const int* p = (const int*)ei;
        r = p[i];
        c = p[(size_t)E + i];
    }
    d_row[i] = r;
    d_col[i] = c;
    atomicAdd(&d_deg[c], 1.0f);
}

__global__ void init_deg_kernel(int n) {
    int i = blockIdx.x * blockDim.x + threadIdx.x;
    if (i < n) d_deg[i] = 1.0f; // self loop
}

__global__ void dinv_kernel(int n) {
    int i = blockIdx.x * blockDim.x + threadIdx.x;
    if (i < n) d_dinv[i] = rsqrtf(d_deg[i]);
}

// ---------------- zero accumulator ----------------
__global__ void zero_kernel(float4* __restrict__ p, int n4) {
    int i = blockIdx.x * blockDim.x + threadIdx.x;
    if (i < n4) p[i] = make_float4(0.f, 0.f, 0.f, 0.f);
}

// ---------------- GEMM: C[i,:] = act( (A[i,:] @ W)*(SCALE?dinv[i]:1) + (BIAS?b:0) ) --
// Register-blocked: R rows per thread, 16 cols per thread (as 8 f32x2 accumulators).
template<int K, int NC, bool RELU, bool BIAS, bool SCALE, int R>
__global__ __launch_bounds__(256) void gemm_kernel(
    const float* __restrict__ A, const float* __restrict__ W,
    const float* __restrict__ bias, float* __restrict__ C, int nrows) {
    constexpr int CG  = NC / 16;           // thread col-groups of 16
    constexpr int RPB = (256 / CG) * R;    // rows per block
    __shared__ float Ws[K * NC];
    for (int t = threadIdx.x; t < K * NC / 4; t += 256)
        ((float4*)Ws)[t] = ((const float4*)W)[t];
    __syncthreads();

    int rg = threadIdx.x / CG;
    int cg = threadIdx.x % CG;
    int r0 = blockIdx.x * RPB + rg * R;

    const float4* Arow[R];
    bool valid[R];
#pragma unroll
    for (int i = 0; i < R; ++i) {
        int r = r0 + i;
        valid[i] = (r < nrows);
        Arow[i] = (const float4*)(A + (size_t)(valid[i] ? r : 0) * K);
    }

    unsigned long long acc[R][8];
#pragma unroll
    for (int i = 0; i < R; ++i)
#pragma unroll
        for (int j = 0; j < 8; ++j) acc[i][j] = 0ull;

#pragma unroll
    for (int k4 = 0; k4 < K / 4; ++k4) {
        float4 a4[R];
#pragma unroll
        for (int i = 0; i < R; ++i) a4[i] = Arow[i][k4];
#pragma unroll
        for (int s = 0; s < 4; ++s) {
            int k = k4 * 4 + s;
            const unsigned long long* w2 =
                (const unsigned long long*)&Ws[k * NC + cg * 16];
            unsigned long long wr[8];
#pragma unroll
            for (int j = 0; j < 8; ++j) wr[j] = w2[j];
#pragma unroll
            for (int i = 0; i < R; ++i) {
                float av = (s == 0) ? a4[i].x : (s == 1) ? a4[i].y
                         : (s == 2) ? a4[i].z : a4[i].w;
                unsigned long long ap = pack2(av);
#pragma unroll
                for (int j = 0; j < 8; ++j) fma2(acc[i][j], ap, wr[j]);
            }
        }
    }

#pragma unroll
    for (int i = 0; i < R; ++i) {
        if (!valid[i]) continue;
        int r = r0 + i;
        float sc = SCALE ? d_dinv[r] : 1.0f;
        float4* Crow = (float4*)(C + (size_t)r * NC + cg * 16);
#pragma unroll
        for (int q = 0; q < 4; ++q) {
            float2 p0 = unpack2(acc[i][q * 2]);
            float2 p1 = unpack2(acc[i][q * 2 + 1]);
            float4 o = make_float4(p0.x * sc, p0.y * sc, p1.x * sc, p1.y * sc);
            if (BIAS) {
                const float4 bb = *(const float4*)&bias[cg * 16 + q * 4];
                o.x += bb.x; o.y += bb.y; o.z += bb.z; o.w += bb.w;
            }
            if (RELU) {
                o.x = fmaxf(o.x, 0.f); o.y = fmaxf(o.y, 0.f);
                o.z = fmaxf(o.z, 0.f); o.w = fmaxf(o.w, 0.f);
            }
            Crow[q] = o;
        }
    }
}

// ---------------- edge scatter: acc[col] += g[row] (2 edges/thread-group ILP) --------
__global__ void scatter_kernel(int E, int half) {
    int tid = blockIdx.x * blockDim.x + threadIdx.x;
    int e = tid >> 4;
    if (e >= half) return;
    int l = (tid & 15) * 4;
    int r0 = d_row[e], c0 = d_col[e];
    int e1 = e + half;
    bool has2 = (e1 < E);
    int r1 = has2 ? d_row[e1] : 0;
    int c1 = has2 ? d_col[e1] : 0;
    float4 v0 = __ldcg((const float4*)&d_g[(size_t)r0 * HID + l]);
    float4 v1 = has2 ? __ldcg((const float4*)&d_g[(size_t)r1 * HID + l])
                     : make_float4(0.f, 0.f, 0.f, 0.f);
    red_add_v4(&d_acc[(size_t)c0 * HID + l], v0);
    if (has2) red_add_v4(&d_acc[(size_t)c1 * HID + l], v1);
}

// ---------------- out[i,:] = relu( dinv[i]*(acc[i,:] + g[i,:]) + b ) ----------------
__global__ void finalize_kernel(const float* __restrict__ b, float* __restrict__ out, int n) {
    int idx = blockIdx.x * blockDim.x + threadIdx.x; // over n*16 float4 groups
    if (idx >= n * 16) return;
    int i  = idx >> 4;
    int j4 = idx & 15;
    float4 a  = *(const float4*)&d_acc[(size_t)idx * 4];
    float4 g  = *(const float4*)&d_g[(size_t)idx * 4];
    float  di = d_dinv[i];
    float4 bb = *(const float4*)&b[j4 * 4];
    float4 o;
    o.x = fmaxf(di * (a.x + g.x) + bb.x, 0.f);
    o.y = fmaxf(di * (a.y + g.y) + bb.y, 0.f);
    o.z = fmaxf(di * (a.z + g.z) + bb.z, 0.f);
    o.w = fmaxf(di * (a.w + g.w) + bb.w, 0.f);
    *(float4*)&out[(size_t)idx * 4] = o;
}

// ---------------- edge scores: es[e] = dot(nr[row[e]], nr[col[e]]) (2-edge ILP) ------
__global__ void escore_kernel(const float* __restrict__ nr, float* __restrict__ es,
                              int E, int half) {
    int tid = blockIdx.x * blockDim.x + threadIdx.x;
    int e = tid >> 4;
    if (e >= half) return;
    int l = (tid & 15) * 4;
    int r0 = d_row[e], c0 = d_col[e];
    int e1 = e + half;
    bool has2 = (e1 < E);
    int r1 = has2 ? d_row[e1] : 0;
    int c1 = has2 ? d_col[e1] : 0;
    float4 a0 = __ldcg((const float4*)&nr[(size_t)r0 * HID + l]);
    float4 b0 = __ldcg((const float4*)&nr[(size_t)c0 * HID + l]);
    float4 a1, b1;
    if (has2) {
        a1 = __ldcg((const float4*)&nr[(size_t)r1 * HID + l]);
        b1 = __ldcg((const float4*)&nr[(size_t)c1 * HID + l]);
    }
    float s0 = a0.x * b0.x + a0.y * b0.y + a0.z * b0.z + a0.w * b0.w;
    float s1 = has2 ? (a1.x * b1.x + a1.y * b1.y + a1.z * b1.z + a1.w * b1.w) : 0.f;
#pragma unroll
    for (int m = 8; m >= 1; m >>= 1) {
        s0 += __shfl_xor_sync(0xffffffffu, s0, m);
        s1 += __shfl_xor_sync(0xffffffffu, s1, m);
    }
    if ((tid & 15) == 0) {
        es[e] = s0;
        if (has2) es[e1] = s1;
    }
}

// ---------------- launch ----------------
extern "C" void kernel_launch(void* const* d_in, const int* in_sizes, int n_in,
                              void* d_out, int out_size) {
    const float* x   = (const float*)d_in[0];
    const void*  ei  = d_in[1];
    const float* W1  = (const float*)d_in[2];
    const float* b1  = (const float*)d_in[3];
    const float* W2  = (const float*)d_in[4];
    const float* b2  = (const float*)d_in[5];
    const float* Wd1 = (const float*)d_in[6];
    const float* bd1 = (const float*)d_in[7];
    const float* Wd2 = (const float*)d_in[8];
    const float* bd2 = (const float*)d_in[9];
    float* out = (float*)d_out;

    int Nn = in_sizes[0] / INCH; // 100000
    int Ee = in_sizes[1] / 2;    // 3200000
    int half = (Ee + 1) / 2;

    float* out_rx = out;
    float* out_es = out + (size_t)Nn * INCH;
    float* out_nr = out_es + (size_t)Ee;

    float *pg = nullptr, *pacc = nullptr, *ph = nullptr;
    cudaGetSymbolAddress((void**)&pg,   d_g);
    cudaGetSymbolAddress((void**)&pacc, d_acc);
    cudaGetSymbolAddress((void**)&ph,   d_h);

    const int T = 256;
    int ebl   = (Ee + T - 1) / T;
    int nbl   = (Nn + T - 1) / T;
    int h16bl = (int)(((size_t)half * 16 + T - 1) / T);
    int n16bl = (int)(((size_t)Nn * 16 + T - 1) / T);
    int n4bl  = (int)(((size_t)Nn * HID / 4 + T - 1) / T);

    // edge index preprocessing + degrees (count fused into convert)
    detect_kernel<<<1, 32>>>((const unsigned*)ei);
    init_deg_kernel<<<nbl, T>>>(Nn);
    convert_kernel<<<ebl, T>>>(ei, Ee);
    dinv_kernel<<<nbl, T>>>(Nn);

    // ---- layer 1: g = (x@W1)*dinv ; acc = scatter(g) ; h = relu(dinv*(acc+g)+b1)
    gemm_kernel<INCH, HID, false, false, true, 4>
        <<<(Nn + 255) / 256, T>>>(x, W1, nullptr, pg, Nn);
    zero_kernel<<<n4bl, T>>>((float4*)pacc, Nn * HID / 4);
    scatter_kernel<<<h16bl, T>>>(Ee, half);
    finalize_kernel<<<n16bl, T>>>(b1, ph, Nn);

    // ---- layer 2 -> node_representation (written straight into out segment)
    gemm_kernel<HID, HID, false, false, true, 4>
        <<<(Nn + 255) / 256, T>>>(ph, W2, nullptr, pg, Nn);
    zero_kernel<<<n4bl, T>>>((float4*)pacc, Nn * HID / 4);
    scatter_kernel<<<h16bl, T>>>(Ee, half);
    finalize_kernel<<<n16bl, T>>>(b2, out_nr, Nn);

    // ---- decoder: rec = relu(nr@Wd1+bd1) ; rx = rec@Wd2 + bd2
    gemm_kernel<HID, HID, true, true, false, 4>
        <<<(Nn + 255) / 256, T>>>(out_nr, Wd1, bd1, ph, Nn);
    gemm_kernel<HID, INCH, false, true, false, 4>
        <<<(Nn + 127) / 128, T>>>(ph, Wd2, bd2, out_rx, Nn);

    // ---- edge scores
    escore_kernel<<<h16bl, T>>>(out_nr, out_es, Ee, half);
}

// round 3
// speedup vs baseline: 2.1484x; 1.1254x over previous
#include <cuda_runtime.h>

#define NNODES 100000
#define NEDGES 3200000
#define INCH 128
#define HID 64

// ---------------- scratch (static device globals; no allocs allowed) ----------------
__device__ float d_g[(size_t)NNODES * HID];    // dinv-scaled features (gather source)
__device__ float d_h[(size_t)NNODES * HID];    // layer intermediate
__device__ float d_dinv[NNODES];
__device__ int   d_cnt[NNODES];                // in-degree (excl self loop)
__device__ int   d_off[NNODES + 1];            // CSR offsets
__device__ int   d_cur[NNODES];                // placement cursors
__device__ int   d_srcs[NEDGES];               // CSR: source node per incoming edge
__device__ int   d_row[NEDGES];
__device__ int   d_col[NEDGES];
__device__ int   g_idx64;

// ---------------- helpers ----------------
__device__ __forceinline__ unsigned long long pack2(float v) {
    unsigned long long r;
    asm("mov.b64 %0, {%1, %1};" : "=l"(r) : "f"(v));
    return r;
}
__device__ __forceinline__ void fma2(unsigned long long& acc, unsigned long long a,
                                     unsigned long long b) {
    asm("fma.rn.f32x2 %0, %1, %2, %0;" : "+l"(acc) : "l"(a), "l"(b));
}
__device__ __forceinline__ float2 unpack2(unsigned long long v) {
    float2 r;
    asm("mov.b64 {%0, %1}, %2;" : "=f"(r.x), "=f"(r.y) : "l"(v));
    return r;
}

// ---------------- dtype detection: int64 edge_index has zero high words --------------
__global__ void detect_kernel(const unsigned* __restrict__ ei) {
    unsigned v = 0;
    int i = threadIdx.x;
#pragma unroll
    for (int s = 0; s < 4; ++s) v |= ei[(size_t)(i * 4 + s) * 2 + 1];
    unsigned any = __ballot_sync(0xffffffffu, v != 0);
    if (threadIdx.x == 0) g_idx64 = (any == 0) ? 1 : 0;
}

__global__ void init_cnt_kernel(int n) {
    int i = blockIdx.x * blockDim.x + threadIdx.x;
    if (i < n) d_cnt[i] = 0;
}

// ---------------- convert + in-degree histogram fused -------------------------------
__global__ void convert_kernel(const void* __restrict__ ei, int E) {
    int i = blockIdx.x * blockDim.x + threadIdx.x;
    if (i >= E) return;
    int r, c;
    if (g_idx64) {
        const long long* p = (const long long*)ei;
        r = (int)p[i];
        c = (int)p[(size_t)E + i];
    } else {
        const int* p = (const int*)ei;
        r = p[i];
        c = p[(size_t)E + i];
    }
    d_row[i] = r;
    d_col[i] = c;
    atomicAdd(&d_cnt[c], 1);
}

__global__ void dinv_kernel(int n) {
    int i = blockIdx.x * blockDim.x + threadIdx.x;
    if (i < n) d_dinv[i] = rsqrtf((float)(d_cnt[i] + 1));
}

// ---------------- single-block exclusive scan over d_cnt -> d_off, d_cur ------------
#define SCAN_T 1024
__global__ void scan_kernel(int n) {
    __shared__ int swarp[32];
    __shared__ int sbase;
    int t = threadIdx.x, lane = t & 31, wid = t >> 5;
    int carry = 0;
    for (int base = 0; base < n; base += SCAN_T) {
        int i = base + t;
        int v = (i < n) ? d_cnt[i] : 0;
        // warp inclusive scan
        int incl = v;
#pragma unroll
        for (int o = 1; o < 32; o <<= 1) {
            int x = __shfl_up_sync(0xffffffffu, incl, o);
            if (lane >= o) incl += x;
        }
        if (lane == 31) swarp[wid] = incl;
        __syncthreads();
        if (wid == 0) {
            int wv = swarp[lane];
            int winc = wv;
#pragma unroll
            for (int o = 1; o < 32; o <<= 1) {
                int x = __shfl_up_sync(0xffffffffu, winc, o);
                if (lane >= o) winc += x;
            }
            swarp[lane] = winc - wv;     // exclusive warp offset
            if (lane == 31) sbase = winc; // block total
        }
        __syncthreads();
        int excl = incl - v + swarp[wid] + carry;
        if (i < n) { d_off[i] = excl; d_cur[i] = excl; }
        carry += sbase;
        __syncthreads();
    }
    if (t == 0) d_off[n] = carry;
}

// ---------------- place edges into CSR ----------------------------------------------
__global__ void place_kernel(int E) {
    int i = blockIdx.x * blockDim.x + threadIdx.x;
    if (i >= E) return;
    int pos = atomicAdd(&d_cur[d_col[i]], 1);
    d_srcs[pos] = d_row[i];
}

// ---------------- GEMM: C[i,:] = act( (A[i,:] @ W)*(SCALE?dinv[i]:1) + (BIAS?b:0) ) --
template<int K, int NC, bool RELU, bool BIAS, bool SCALE, int R>
__global__ __launch_bounds__(256) void gemm_kernel(
    const float* __restrict__ A, const float* __restrict__ W,
    const float* __restrict__ bias, float* __restrict__ C, int nrows) {
    constexpr int CG  = NC / 16;
    constexpr int RPB = (256 / CG) * R;
    __shared__ float Ws[K * NC];
    for (int t = threadIdx.x; t < K * NC / 4; t += 256)
        ((float4*)Ws)[t] = ((const float4*)W)[t];
    __syncthreads();

    int rg = threadIdx.x / CG;
    int cg = threadIdx.x % CG;
    int r0 = blockIdx.x * RPB + rg * R;

    const float4* Arow[R];
    bool valid[R];
#pragma unroll
    for (int i = 0; i < R; ++i) {
        int r = r0 + i;
        valid[i] = (r < nrows);
        Arow[i] = (const float4*)(A + (size_t)(valid[i] ? r : 0) * K);
    }

    unsigned long long acc[R][8];
#pragma unroll
    for (int i = 0; i < R; ++i)
#pragma unroll
        for (int j = 0; j < 8; ++j) acc[i][j] = 0ull;

#pragma unroll
    for (int k4 = 0; k4 < K / 4; ++k4) {
        float4 a4[R];
#pragma unroll
        for (int i = 0; i < R; ++i) a4[i] = Arow[i][k4];
#pragma unroll
        for (int s = 0; s < 4; ++s) {
            int k = k4 * 4 + s;
            const unsigned long long* w2 =
                (const unsigned long long*)&Ws[k * NC + cg * 16];
            unsigned long long wr[8];
#pragma unroll
            for (int j = 0; j < 8; ++j) wr[j] = w2[j];
#pragma unroll
            for (int i = 0; i < R; ++i) {
                float av = (s == 0) ? a4[i].x : (s == 1) ? a4[i].y
                         : (s == 2) ? a4[i].z : a4[i].w;
                unsigned long long ap = pack2(av);
#pragma unroll
                for (int j = 0; j < 8; ++j) fma2(acc[i][j], ap, wr[j]);
            }
        }
    }

#pragma unroll
    for (int i = 0; i < R; ++i) {
        if (!valid[i]) continue;
        int r = r0 + i;
        float sc = SCALE ? d_dinv[r] : 1.0f;
        float4* Crow = (float4*)(C + (size_t)r * NC + cg * 16);
#pragma unroll
        for (int q = 0; q < 4; ++q) {
            float2 p0 = unpack2(acc[i][q * 2]);
            float2 p1 = unpack2(acc[i][q * 2 + 1]);
            float4 o = make_float4(p0.x * sc, p0.y * sc, p1.x * sc, p1.y * sc);
            if (BIAS) {
                const float4 bb = *(const float4*)&bias[cg * 16 + q * 4];
                o.x += bb.x; o.y += bb.y; o.z += bb.z; o.w += bb.w;
            }
            if (RELU) {
                o.x = fmaxf(o.x, 0.f); o.y = fmaxf(o.y, 0.f);
                o.z = fmaxf(o.z, 0.f); o.w = fmaxf(o.w, 0.f);
            }
            Crow[q] = o;
        }
    }
}

// ---------------- CSR gather: out[c] = relu(dinv[c]*(sum_in g[r] + g[c]) + b) --------
// One warp per node; each lane owns 2 feature columns (float2).
__global__ __launch_bounds__(256) void gather_csr_kernel(
    const float* __restrict__ b, float* __restrict__ out, int n) {
    int warp = (blockIdx.x * blockDim.x + threadIdx.x) >> 5;
    if (warp >= n) return;
    int lane = threadIdx.x & 31;
    int start = d_off[warp];
    int end   = d_off[warp + 1];

    float2 acc0 = make_float2(0.f, 0.f), acc1 = make_float2(0.f, 0.f);
    int p = start;
    for (; p + 1 < end; p += 2) {
        int r0 = d_srcs[p];
        int r1 = d_srcs[p + 1];
        float2 v0 = __ldcg((const float2*)&d_g[(size_t)r0 * HID + lane * 2]);
        float2 v1 = __ldcg((const float2*)&d_g[(size_t)r1 * HID + lane * 2]);
        acc0.x += v0.x; acc0.y += v0.y;
        acc1.x += v1.x; acc1.y += v1.y;
    }
    if (p < end) {
        int r0 = d_srcs[p];
        float2 v0 = __ldcg((const float2*)&d_g[(size_t)r0 * HID + lane * 2]);
        acc0.x += v0.x; acc0.y += v0.y;
    }
    // self loop
    float2 gs = *(const float2*)&d_g[(size_t)warp * HID + lane * 2];
    float di = d_dinv[warp];
    float2 bb = *(const float2*)&b[lane * 2];
    float2 o;
    o.x = fmaxf(di * (acc0.x + acc1.x + gs.x) + bb.x, 0.f);
    o.y = fmaxf(di * (acc0.y + acc1.y + gs.y) + bb.y, 0.f);
    *(float2*)&out[(size_t)warp * HID + lane * 2] = o;
}

// ---------------- edge scores: es[e] = dot(nr[row[e]], nr[col[e]]) (2-edge ILP) ------
__global__ void escore_kernel(const float* __restrict__ nr, float* __restrict__ es,
                              int E, int half) {
    int tid = blockIdx.x * blockDim.x + threadIdx.x;
    int e = tid >> 4;
    if (e >= half) return;
    int l = (tid & 15) * 4;
    int r0 = d_row[e], c0 = d_col[e];
    int e1 = e + half;
    bool has2 = (e1 < E);
    int r1 = has2 ? d_row[e1] : 0;
    int c1 = has2 ? d_col[e1] : 0;
    float4 a0 = __ldcg((const float4*)&nr[(size_t)r0 * HID + l]);
    float4 b0 = __ldcg((const float4*)&nr[(size_t)c0 * HID + l]);
    float4 a1, b1;
    if (has2) {
        a1 = __ldcg((const float4*)&nr[(size_t)r1 * HID + l]);
        b1 = __ldcg((const float4*)&nr[(size_t)c1 * HID + l]);
    }
    float s0 = a0.x * b0.x + a0.y * b0.y + a0.z * b0.z + a0.w * b0.w;
    float s1 = has2 ? (a1.x * b1.x + a1.y * b1.y + a1.z * b1.z + a1.w * b1.w) : 0.f;
#pragma unroll
    for (int m = 8; m >= 1; m >>= 1) {
        s0 += __shfl_xor_sync(0xffffffffu, s0, m);
        s1 += __shfl_xor_sync(0xffffffffu, s1, m);
    }
    if ((tid & 15) == 0) {
        es[e] = s0;
        if (has2) es[e1] = s1;
    }
}

// ---------------- launch ----------------
extern "C" void kernel_launch(void* const* d_in, const int* in_sizes, int n_in,
                              void* d_out, int out_size) {
    const float* x   = (const float*)d_in[0];
    const void*  ei  = d_in[1];
    const float* W1  = (const float*)d_in[2];
    const float* b1  = (const float*)d_in[3];
    const float* W2  = (const float*)d_in[4];
    const float* b2  = (const float*)d_in[5];
    const float* Wd1 = (const float*)d_in[6];
    const float* bd1 = (const float*)d_in[7];
    const float* Wd2 = (const float*)d_in[8];
    const float* bd2 = (const float*)d_in[9];
    float* out = (float*)d_out;

    int Nn = in_sizes[0] / INCH; // 100000
    int Ee = in_sizes[1] / 2;    // 3200000
    int half = (Ee + 1) / 2;

    float* out_rx = out;
    float* out_es = out + (size_t)Nn * INCH;
    float* out_nr = out_es + (size_t)Ee;

    float *pg = nullptr, *ph = nullptr;
    cudaGetSymbolAddress((void**)&pg, d_g);
    cudaGetSymbolAddress((void**)&ph, d_h);

    const int T = 256;
    int ebl   = (Ee + T - 1) / T;
    int nbl   = (Nn + T - 1) / T;
    int h16bl = (int)(((size_t)half * 16 + T - 1) / T);
    int nwbl  = (int)(((size_t)Nn * 32 + T - 1) / T); // warp per node

    // edge index preprocessing: convert + histogram, dinv, CSR build
    detect_kernel<<<1, 32>>>((const unsigned*)ei);
    init_cnt_kernel<<<nbl, T>>>(Nn);
    convert_kernel<<<ebl, T>>>(ei, Ee);
    dinv_kernel<<<nbl, T>>>(Nn);
    scan_kernel<<<1, SCAN_T>>>(Nn);
    place_kernel<<<ebl, T>>>(Ee);

    // ---- layer 1: g = (x@W1)*dinv ; h = relu(dinv*(csr_sum(g)+g)+b1)
    gemm_kernel<INCH, HID, false, false, true, 4>
        <<<(Nn + 255) / 256, T>>>(x, W1, nullptr, pg, Nn);
    gather_csr_kernel<<<nwbl, T>>>(b1, ph, Nn);

    // ---- layer 2 -> node_representation (written straight into out segment)
    gemm_kernel<HID, HID, false, false, true, 4>
        <<<(Nn + 255) / 256, T>>>(ph, W2, nullptr, pg, Nn);
    gather_csr_kernel<<<nwbl, T>>>(b2, out_nr, Nn);

    // ---- decoder: rec = relu(nr@Wd1+bd1) ; rx = rec@Wd2 + bd2
    gemm_kernel<HID, HID, true, true, false, 4>
        <<<(Nn + 255) / 256, T>>>(out_nr, Wd1, bd1, ph, Nn);
    gemm_kernel<HID, INCH, false, true, false, 4>
        <<<(Nn + 127) / 128, T>>>(ph, Wd2, bd2, out_rx, Nn);

    // ---- edge scores
    escore_kernel<<<h16bl, T>>>(out_nr, out_es, Ee, half);
}